// round 1
// baseline (speedup 1.0000x reference)
#include <cuda_runtime.h>
#include <cuda_bf16.h>
#include <math.h>

// Problem constants
#define BATCH 2
#define SEQ   2048
#define HID   1024
#define NH    16
#define HD    64
#define MROWS (BATCH * SEQ)   // 4096

static const size_t OUT_ELEMS  = (size_t)BATCH * SEQ * HID;            // 4,194,304
static const size_t ATTN_ELEMS = (size_t)BATCH * NH * SEQ * (size_t)SEQ; // 134,217,728

// Scratch (allocation-free: __device__ globals)
__device__ float g_q[MROWS * HID];
__device__ float g_k[MROWS * HID];
__device__ float g_v[MROWS * HID];
__device__ float g_ctx[MROWS * HID];
__device__ float g_attn_scratch[(size_t)BATCH * NH * SEQ * (size_t)SEQ]; // fallback if harness doesn't want attn

// ---------------------------------------------------------------------------
// GEMM: C[M,N] = A[M,K] @ B[N,K]^T + bias[N]
// Both A and B are row-major with K contiguous (exactly the x @ W.T layout).
// 64x64 tile, BK=16, 256 threads, 4x4 per thread.
// ---------------------------------------------------------------------------
__global__ __launch_bounds__(256) void gemm_bias_at(
    const float* __restrict__ A, const float* __restrict__ Bw,
    const float* __restrict__ bias, float* __restrict__ C,
    int M, int N, int K)
{
    __shared__ float As[16][65];
    __shared__ float Bs[16][65];

    const int tid = threadIdx.x;
    const int tx = tid & 15, ty = tid >> 4;
    const int m0 = blockIdx.y * 64, n0 = blockIdx.x * 64;

    float acc[4][4] = {};

    for (int k0 = 0; k0 < K; k0 += 16) {
        #pragma unroll
        for (int l = tid; l < 64 * 16; l += 256) {
            int m = l >> 4, k = l & 15;
            As[k][m] = A[(size_t)(m0 + m) * K + (k0 + k)];
        }
        #pragma unroll
        for (int l = tid; l < 64 * 16; l += 256) {
            int n = l >> 4, k = l & 15;
            Bs[k][n] = Bw[(size_t)(n0 + n) * K + (k0 + k)];
        }
        __syncthreads();

        #pragma unroll
        for (int k = 0; k < 16; k++) {
            float ra[4], rb[4];
            #pragma unroll
            for (int i = 0; i < 4; i++) ra[i] = As[k][ty * 4 + i];
            #pragma unroll
            for (int j = 0; j < 4; j++) rb[j] = Bs[k][tx * 4 + j];
            #pragma unroll
            for (int i = 0; i < 4; i++)
                #pragma unroll
                for (int j = 0; j < 4; j++)
                    acc[i][j] = fmaf(ra[i], rb[j], acc[i][j]);
        }
        __syncthreads();
    }

    #pragma unroll
    for (int i = 0; i < 4; i++) {
        int m = m0 + ty * 4 + i;
        #pragma unroll
        for (int j = 0; j < 4; j++) {
            int n = n0 + tx * 4 + j;
            C[(size_t)m * N + n] = acc[i][j] + bias[n];
        }
    }
}

// ---------------------------------------------------------------------------
// Scores: attn_raw[bh, i, j] = sqrt(HD) * dot(Q[bh,i,:], K[bh,j,:])
// Q/K live interleaved in [B*S, HID] with head h at columns h*HD..h*HD+63.
// Blocks fully above the diagonal are skipped (softmax writes their zeros).
// ---------------------------------------------------------------------------
__global__ __launch_bounds__(256) void scores_kernel(
    const float* __restrict__ q, const float* __restrict__ k,
    float* __restrict__ attn)
{
    const int bh = blockIdx.z;
    const int b = bh / NH, h = bh % NH;
    const int m0 = blockIdx.y * 64, n0 = blockIdx.x * 64;
    if (n0 > m0 + 63) return;  // fully-masked tile

    const float* Q  = q + (size_t)b * SEQ * HID + h * HD;
    const float* Kp = k + (size_t)b * SEQ * HID + h * HD;
    float* Crow = attn + (size_t)bh * SEQ * SEQ;

    __shared__ float Qs[64][65];
    __shared__ float Ks[64][65];

    const int tid = threadIdx.x;
    const int tx = tid & 15, ty = tid >> 4;

    for (int l = tid; l < 64 * 64; l += 256) {
        int r = l >> 6, c = l & 63;
        Qs[c][r] = Q[(size_t)(m0 + r) * HID + c];
        Ks[c][r] = Kp[(size_t)(n0 + r) * HID + c];
    }
    __syncthreads();

    float acc[4][4] = {};
    #pragma unroll
    for (int kk = 0; kk < 64; kk++) {
        float ra[4], rb[4];
        #pragma unroll
        for (int i = 0; i < 4; i++) ra[i] = Qs[kk][ty * 4 + i];
        #pragma unroll
        for (int j = 0; j < 4; j++) rb[j] = Ks[kk][tx * 4 + j];
        #pragma unroll
        for (int i = 0; i < 4; i++)
            #pragma unroll
            for (int j = 0; j < 4; j++)
                acc[i][j] = fmaf(ra[i], rb[j], acc[i][j]);
    }

    const float scale = 8.0f;  // sqrt(HD) = sqrt(64)
    #pragma unroll
    for (int i = 0; i < 4; i++) {
        int gi = m0 + ty * 4 + i;
        #pragma unroll
        for (int j = 0; j < 4; j++) {
            int gj = n0 + tx * 4 + j;
            Crow[(size_t)gi * SEQ + gj] = acc[i][j] * scale;  // upper-tri garbage overwritten by softmax
        }
    }
}

// ---------------------------------------------------------------------------
// Row softmax (causal). One block per row. Row cached in smem.
// Writes full row: probs for j<=i, exact 0 for j>i.
// ---------------------------------------------------------------------------
__global__ __launch_bounds__(256) void softmax_kernel(float* __restrict__ attn)
{
    const int i  = blockIdx.x;
    const int bh = blockIdx.y;
    float* row = attn + ((size_t)bh * SEQ + i) * SEQ;
    const int n = i + 1;

    __shared__ float buf[SEQ];
    __shared__ float sred[8];

    const int tid = threadIdx.x;
    const int lane = tid & 31, wrp = tid >> 5;

    // pass 1: load + max
    float lmax = -INFINITY;
    for (int j = tid; j < n; j += 256) {
        float v = row[j];
        buf[j] = v;
        lmax = fmaxf(lmax, v);
    }
    #pragma unroll
    for (int o = 16; o; o >>= 1) lmax = fmaxf(lmax, __shfl_xor_sync(0xffffffffu, lmax, o));
    if (lane == 0) sred[wrp] = lmax;
    __syncthreads();
    float m = fmaxf(fmaxf(fmaxf(sred[0], sred[1]), fmaxf(sred[2], sred[3])),
                    fmaxf(fmaxf(sred[4], sred[5]), fmaxf(sred[6], sred[7])));
    __syncthreads();

    // pass 2: exp + sum
    float lsum = 0.0f;
    for (int j = tid; j < n; j += 256) {
        float e = __expf(buf[j] - m);
        buf[j] = e;
        lsum += e;
    }
    #pragma unroll
    for (int o = 16; o; o >>= 1) lsum += __shfl_xor_sync(0xffffffffu, lsum, o);
    if (lane == 0) sred[wrp] = lsum;
    __syncthreads();
    float tot = sred[0] + sred[1] + sred[2] + sred[3] + sred[4] + sred[5] + sred[6] + sred[7];
    const float inv = 1.0f / tot;
    __syncthreads();

    // pass 3: write normalized + zeros
    for (int j = tid; j < n; j += 256) row[j] = buf[j] * inv;
    for (int j = n + tid; j < SEQ; j += 256) row[j] = 0.0f;
}

// ---------------------------------------------------------------------------
// ctx[bh, i, d] = sum_j attn[bh,i,j] * V[bh,j,d]. Causal: k-loop stops after
// the diagonal tile (upper entries are exact zeros so diag tile is safe).
// ---------------------------------------------------------------------------
__global__ __launch_bounds__(256) void ctx_kernel(
    const float* __restrict__ attn, const float* __restrict__ v,
    float* __restrict__ ctx)
{
    const int m0 = blockIdx.x * 64;
    const int bh = blockIdx.y;
    const int b = bh / NH, h = bh % NH;

    const float* Arow = attn + (size_t)bh * SEQ * SEQ;
    const float* V = v + (size_t)b * SEQ * HID + h * HD;

    __shared__ float As[16][65];
    __shared__ float Bs[16][65];

    const int tid = threadIdx.x;
    const int tx = tid & 15, ty = tid >> 4;

    float acc[4][4] = {};
    const int kmax = m0 + 64;  // causal bound

    for (int k0 = 0; k0 < kmax; k0 += 16) {
        #pragma unroll
        for (int l = tid; l < 64 * 16; l += 256) {
            int m = l >> 4, k = l & 15;
            As[k][m] = Arow[(size_t)(m0 + m) * SEQ + (k0 + k)];
        }
        #pragma unroll
        for (int l = tid; l < 16 * 64; l += 256) {
            int kk = l >> 6, n = l & 63;
            Bs[kk][n] = V[(size_t)(k0 + kk) * HID + n];
        }
        __syncthreads();

        #pragma unroll
        for (int k = 0; k < 16; k++) {
            float ra[4], rb[4];
            #pragma unroll
            for (int i = 0; i < 4; i++) ra[i] = As[k][ty * 4 + i];
            #pragma unroll
            for (int j = 0; j < 4; j++) rb[j] = Bs[k][tx * 4 + j];
            #pragma unroll
            for (int i = 0; i < 4; i++)
                #pragma unroll
                for (int j = 0; j < 4; j++)
                    acc[i][j] = fmaf(ra[i], rb[j], acc[i][j]);
        }
        __syncthreads();
    }

    #pragma unroll
    for (int i = 0; i < 4; i++) {
        int gi = m0 + ty * 4 + i;
        #pragma unroll
        for (int j = 0; j < 4; j++) {
            int gd = tx * 4 + j;
            ctx[((size_t)b * SEQ + gi) * HID + h * HD + gd] = acc[i][j];
        }
    }
}

// ---------------------------------------------------------------------------
extern "C" void kernel_launch(void* const* d_in, const int* in_sizes, int n_in,
                              void* d_out, int out_size)
{
    const float* x  = (const float*)d_in[0];
    const float* Wq = (const float*)d_in[1];
    const float* bq = (const float*)d_in[2];
    const float* Wk = (const float*)d_in[3];
    const float* bk = (const float*)d_in[4];
    const float* Wv = (const float*)d_in[5];
    const float* bv = (const float*)d_in[6];
    const float* Wo = (const float*)d_in[7];
    const float* bo = (const float*)d_in[8];

    float* out = (float*)d_out;

    // Scratch pointers from device symbols (no allocation)
    void *pq, *pk, *pv, *pctx, *pattn_scratch;
    cudaGetSymbolAddress(&pq, g_q);
    cudaGetSymbolAddress(&pk, g_k);
    cudaGetSymbolAddress(&pv, g_v);
    cudaGetSymbolAddress(&pctx, g_ctx);
    cudaGetSymbolAddress(&pattn_scratch, g_attn_scratch);

    // attn goes to d_out (after `out`) if the harness expects the tuple,
    // otherwise into scratch.
    float* attn = ((size_t)out_size >= OUT_ELEMS + ATTN_ELEMS)
                      ? out + OUT_ELEMS
                      : (float*)pattn_scratch;

    dim3 gProj(HID / 64, MROWS / 64);  // (16, 64)

    gemm_bias_at<<<gProj, 256>>>(x, Wq, bq, (float*)pq, MROWS, HID, HID);
    gemm_bias_at<<<gProj, 256>>>(x, Wk, bk, (float*)pk, MROWS, HID, HID);
    gemm_bias_at<<<gProj, 256>>>(x, Wv, bv, (float*)pv, MROWS, HID, HID);

    dim3 gScores(SEQ / 64, SEQ / 64, BATCH * NH);  // (32, 32, 32)
    scores_kernel<<<gScores, 256>>>((const float*)pq, (const float*)pk, attn);

    dim3 gSoftmax(SEQ, BATCH * NH);  // (2048, 32)
    softmax_kernel<<<gSoftmax, 256>>>(attn);

    dim3 gCtx(SEQ / 64, BATCH * NH);  // (32, 32)
    ctx_kernel<<<gCtx, 256>>>(attn, (const float*)pv, (float*)pctx);

    gemm_bias_at<<<gProj, 256>>>((const float*)pctx, Wo, bo, out, MROWS, HID, HID);
}

// round 2
// speedup vs baseline: 1.5120x; 1.5120x over previous
#include <cuda_runtime.h>
#include <cuda_bf16.h>
#include <math.h>

// Problem constants
#define BATCH 2
#define SEQ   2048
#define HID   1024
#define NH    16
#define HD    64
#define MROWS (BATCH * SEQ)   // 4096

static const size_t OUT_ELEMS  = (size_t)BATCH * SEQ * HID;              // 4,194,304
static const size_t ATTN_ELEMS = (size_t)BATCH * NH * SEQ * (size_t)SEQ; // 134,217,728

// Scratch (allocation-free: __device__ globals)
__device__ float g_q[MROWS * HID];
__device__ float g_k[MROWS * HID];
__device__ float g_v[MROWS * HID];
__device__ float g_ctx[MROWS * HID];
__device__ float g_attn_scratch[(size_t)BATCH * NH * SEQ * (size_t)SEQ];

// ---------------------------------------------------------------------------
// f32x2 packed-FMA helpers (sm_100+): 2 fp32 FMAs per instruction.
// ---------------------------------------------------------------------------
typedef unsigned long long ull;

__device__ __forceinline__ ull dup2(float a) {
    ull r; asm("mov.b64 %0, {%1, %1};" : "=l"(r) : "f"(a)); return r;
}
__device__ __forceinline__ ull pk2(float x, float y) {
    ull r; asm("mov.b64 %0, {%1, %2};" : "=l"(r) : "f"(x), "f"(y)); return r;
}
__device__ __forceinline__ void ffma2(ull& d, ull a, ull b) {
    asm("fma.rn.f32x2 %0, %1, %2, %3;" : "=l"(d) : "l"(a), "l"(b), "l"(d));
}
__device__ __forceinline__ float2 unp2(ull v) {
    float2 f; asm("mov.b64 {%0, %1}, %2;" : "=f"(f.x), "=f"(f.y) : "l"(v)); return f;
}

// ---------------------------------------------------------------------------
// GEMM: C[M,N] = A[M,K] @ B[N,K]^T + bias[N]
// 128x128 tile, BK=16, 256 threads, 8x8 per thread, f32x2 packed FMA,
// register-staged global prefetch.
// ---------------------------------------------------------------------------
__global__ __launch_bounds__(256, 2) void gemm128(
    const float* __restrict__ A, const float* __restrict__ Bw,
    const float* __restrict__ bias, float* __restrict__ C,
    int M, int N, int K)
{
    __shared__ float As[16][132];
    __shared__ float Bs[16][132];

    const int tid = threadIdx.x;
    const int tx = tid & 15, ty = tid >> 4;
    const int m0 = blockIdx.y * 128, n0 = blockIdx.x * 128;

    const int lr = tid >> 2;         // 0..63
    const int lc = (tid & 3) << 2;   // 0,4,8,12

    const float* Ab = A + (size_t)(m0 + lr) * K + lc;
    const float* Bb = Bw + (size_t)(n0 + lr) * K + lc;
    const size_t rowskip = (size_t)64 * K;

    float4 pa0 = *(const float4*)(Ab);
    float4 pa1 = *(const float4*)(Ab + rowskip);
    float4 pb0 = *(const float4*)(Bb);
    float4 pb1 = *(const float4*)(Bb + rowskip);

    ull acc[8][4];
    #pragma unroll
    for (int i = 0; i < 8; i++)
        #pragma unroll
        for (int j = 0; j < 4; j++) acc[i][j] = 0ull;

    for (int k0 = 0; k0 < K; k0 += 16) {
        // stage to smem (transposed)
        As[lc + 0][lr] = pa0.x; As[lc + 1][lr] = pa0.y;
        As[lc + 2][lr] = pa0.z; As[lc + 3][lr] = pa0.w;
        As[lc + 0][lr + 64] = pa1.x; As[lc + 1][lr + 64] = pa1.y;
        As[lc + 2][lr + 64] = pa1.z; As[lc + 3][lr + 64] = pa1.w;
        Bs[lc + 0][lr] = pb0.x; Bs[lc + 1][lr] = pb0.y;
        Bs[lc + 2][lr] = pb0.z; Bs[lc + 3][lr] = pb0.w;
        Bs[lc + 0][lr + 64] = pb1.x; Bs[lc + 1][lr + 64] = pb1.y;
        Bs[lc + 2][lr + 64] = pb1.z; Bs[lc + 3][lr + 64] = pb1.w;
        __syncthreads();

        if (k0 + 16 < K) {
            pa0 = *(const float4*)(Ab + k0 + 16);
            pa1 = *(const float4*)(Ab + rowskip + k0 + 16);
            pb0 = *(const float4*)(Bb + k0 + 16);
            pb1 = *(const float4*)(Bb + rowskip + k0 + 16);
        }

        #pragma unroll
        for (int k = 0; k < 16; k++) {
            float4 a0 = *(float4*)&As[k][ty * 8];
            float4 a1 = *(float4*)&As[k][ty * 8 + 4];
            float4 b0 = *(float4*)&Bs[k][tx * 8];
            float4 b1 = *(float4*)&Bs[k][tx * 8 + 4];
            ull bp0 = pk2(b0.x, b0.y), bp1 = pk2(b0.z, b0.w);
            ull bp2 = pk2(b1.x, b1.y), bp3 = pk2(b1.z, b1.w);
            float av[8] = {a0.x, a0.y, a0.z, a0.w, a1.x, a1.y, a1.z, a1.w};
            #pragma unroll
            for (int i = 0; i < 8; i++) {
                ull ad = dup2(av[i]);
                ffma2(acc[i][0], ad, bp0);
                ffma2(acc[i][1], ad, bp1);
                ffma2(acc[i][2], ad, bp2);
                ffma2(acc[i][3], ad, bp3);
            }
        }
        __syncthreads();
    }

    float4 bia0 = *(const float4*)&bias[n0 + tx * 8];
    float4 bia1 = *(const float4*)&bias[n0 + tx * 8 + 4];

    #pragma unroll
    for (int i = 0; i < 8; i++) {
        int m = m0 + ty * 8 + i;
        float2 c0 = unp2(acc[i][0]), c1 = unp2(acc[i][1]);
        float2 c2 = unp2(acc[i][2]), c3 = unp2(acc[i][3]);
        float4 o0 = make_float4(c0.x + bia0.x, c0.y + bia0.y, c1.x + bia0.z, c1.y + bia0.w);
        float4 o1 = make_float4(c2.x + bia1.x, c2.y + bia1.y, c3.x + bia1.z, c3.y + bia1.w);
        *(float4*)&C[(size_t)m * N + n0 + tx * 8]     = o0;
        *(float4*)&C[(size_t)m * N + n0 + tx * 8 + 4] = o1;
    }
}

// ---------------------------------------------------------------------------
// Fused causal attention per (bh, 64-row tile):
//  phase 1: S = 8 * Q K^T tiles -> raw stash to attn gmem, online (m,l)
//  phase 2: re-read raw S (L1/L2-hot, same thread), p = exp(s-m)/l,
//           write probs, accumulate ctx += p V
//  epilogue: ctx write + vectorized zero-fill of masked columns
// ---------------------------------------------------------------------------
#define SD 68

__global__ __launch_bounds__(256, 3) void attn_fused(
    const float* __restrict__ q, const float* __restrict__ k,
    const float* __restrict__ v, float* __restrict__ attn,
    float* __restrict__ ctx)
{
    __shared__ float Qs[64][SD];   // phase1: [d][i] Q^T ; phase2: [j][i] P^T
    __shared__ float KVs[64][SD];  // phase1: [d][j] K^T ; phase2: [j][d] V

    const int tid = threadIdx.x;
    const int tx = tid & 15, ty = tid >> 4;
    const int mt = blockIdx.x;
    const int bh = blockIdx.y;
    const int b = bh >> 4, h = bh & 15;
    const int m0 = mt * 64;

    const float* Q  = q + (size_t)b * SEQ * HID + h * HD;
    const float* Kp = k + (size_t)b * SEQ * HID + h * HD;
    const float* Vp = v + (size_t)b * SEQ * HID + h * HD;
    float* arow = attn + (size_t)bh * SEQ * SEQ;

    // load Q tile transposed: Qs[d][i]
    for (int it = tid; it < 64 * 16; it += 256) {
        int r = it >> 4;
        int c = (it & 15) << 2;
        float4 vq = *(const float4*)&Q[(size_t)(m0 + r) * HID + c];
        Qs[c + 0][r] = vq.x; Qs[c + 1][r] = vq.y;
        Qs[c + 2][r] = vq.z; Qs[c + 3][r] = vq.w;
    }

    float m_[4] = {-INFINITY, -INFINITY, -INFINITY, -INFINITY};
    float l_[4] = {0.f, 0.f, 0.f, 0.f};

    // ---------------- phase 1 ----------------
    for (int jt = 0; jt <= mt; jt++) {
        for (int it = tid; it < 64 * 16; it += 256) {
            int r = it >> 4;
            int c = (it & 15) << 2;
            float4 kv = *(const float4*)&Kp[(size_t)(jt * 64 + r) * HID + c];
            KVs[c + 0][r] = kv.x; KVs[c + 1][r] = kv.y;
            KVs[c + 2][r] = kv.z; KVs[c + 3][r] = kv.w;
        }
        __syncthreads();

        ull sacc[4][2];
        #pragma unroll
        for (int i = 0; i < 4; i++) { sacc[i][0] = 0ull; sacc[i][1] = 0ull; }

        #pragma unroll
        for (int d = 0; d < 64; d++) {
            float4 qa = *(float4*)&Qs[d][ty * 4];
            float4 kb = *(float4*)&KVs[d][tx * 4];
            ull b01 = pk2(kb.x, kb.y), b23 = pk2(kb.z, kb.w);
            float qv[4] = {qa.x, qa.y, qa.z, qa.w};
            #pragma unroll
            for (int i = 0; i < 4; i++) {
                ull ad = dup2(qv[i]);
                ffma2(sacc[i][0], ad, b01);
                ffma2(sacc[i][1], ad, b23);
            }
        }

        const int gj0 = jt * 64 + tx * 4;
        #pragma unroll
        for (int ii = 0; ii < 4; ii++) {
            float2 p0 = unp2(sacc[ii][0]);
            float2 p1 = unp2(sacc[ii][1]);
            float s0 = p0.x * 8.0f, s1 = p0.y * 8.0f;
            float s2 = p1.x * 8.0f, s3 = p1.y * 8.0f;
            const int gi = m0 + ty * 4 + ii;

            // raw stash (masked entries overwritten with 0 in phase 2)
            *(float4*)&arow[(size_t)gi * SEQ + gj0] = make_float4(s0, s1, s2, s3);

            float t0 = (gj0 + 0 > gi) ? -INFINITY : s0;
            float t1 = (gj0 + 1 > gi) ? -INFINITY : s1;
            float t2 = (gj0 + 2 > gi) ? -INFINITY : s2;
            float t3 = (gj0 + 3 > gi) ? -INFINITY : s3;

            float tm = fmaxf(fmaxf(t0, t1), fmaxf(t2, t3));
            #pragma unroll
            for (int o = 1; o < 16; o <<= 1)
                tm = fmaxf(tm, __shfl_xor_sync(0xffffffffu, tm, o));
            float mnew = fmaxf(m_[ii], tm);

            float es = __expf(t0 - mnew) + __expf(t1 - mnew) +
                       __expf(t2 - mnew) + __expf(t3 - mnew);
            #pragma unroll
            for (int o = 1; o < 16; o <<= 1)
                es += __shfl_xor_sync(0xffffffffu, es, o);

            l_[ii] = l_[ii] * __expf(m_[ii] - mnew) + es;
            m_[ii] = mnew;
        }
        __syncthreads();
    }

    float invl[4];
    #pragma unroll
    for (int ii = 0; ii < 4; ii++) invl[ii] = 1.0f / l_[ii];

    // ---------------- phase 2 ----------------
    ull cacc[4][2];
    #pragma unroll
    for (int i = 0; i < 4; i++) { cacc[i][0] = 0ull; cacc[i][1] = 0ull; }

    for (int jt = 0; jt <= mt; jt++) {
        // V tile, natural layout [j][d]
        for (int it = tid; it < 64 * 16; it += 256) {
            int r = it >> 4;
            int c = (it & 15) << 2;
            *(float4*)&KVs[r][c] = *(const float4*)&Vp[(size_t)(jt * 64 + r) * HID + c];
        }

        const int gj0 = jt * 64 + tx * 4;
        #pragma unroll
        for (int ii = 0; ii < 4; ii++) {
            const int gi = m0 + ty * 4 + ii;
            float4 s = *(float4*)&arow[(size_t)gi * SEQ + gj0];
            float p0 = (gj0 + 0 > gi) ? 0.f : __expf(s.x - m_[ii]) * invl[ii];
            float p1 = (gj0 + 1 > gi) ? 0.f : __expf(s.y - m_[ii]) * invl[ii];
            float p2 = (gj0 + 2 > gi) ? 0.f : __expf(s.z - m_[ii]) * invl[ii];
            float p3 = (gj0 + 3 > gi) ? 0.f : __expf(s.w - m_[ii]) * invl[ii];
            *(float4*)&arow[(size_t)gi * SEQ + gj0] = make_float4(p0, p1, p2, p3);
            // stage P^T (reuse Qs buffer)
            Qs[tx * 4 + 0][ty * 4 + ii] = p0;
            Qs[tx * 4 + 1][ty * 4 + ii] = p1;
            Qs[tx * 4 + 2][ty * 4 + ii] = p2;
            Qs[tx * 4 + 3][ty * 4 + ii] = p3;
        }
        __syncthreads();

        #pragma unroll
        for (int j = 0; j < 64; j++) {
            float4 pv = *(float4*)&Qs[j][ty * 4];
            float4 vv = *(float4*)&KVs[j][tx * 4];
            ull v01 = pk2(vv.x, vv.y), v23 = pk2(vv.z, vv.w);
            float pvv[4] = {pv.x, pv.y, pv.z, pv.w};
            #pragma unroll
            for (int i = 0; i < 4; i++) {
                ull ad = dup2(pvv[i]);
                ffma2(cacc[i][0], ad, v01);
                ffma2(cacc[i][1], ad, v23);
            }
        }
        __syncthreads();
    }

    // write ctx
    #pragma unroll
    for (int ii = 0; ii < 4; ii++) {
        int gi = m0 + ty * 4 + ii;
        float2 c0 = unp2(cacc[ii][0]);
        float2 c1 = unp2(cacc[ii][1]);
        *(float4*)&ctx[((size_t)b * SEQ + gi) * HID + h * HD + tx * 4] =
            make_float4(c0.x, c0.y, c1.x, c1.y);
    }

    // zero-fill masked columns (fully above-diagonal region)
    const int zstart = (mt + 1) * 64;
    const int zcols = SEQ - zstart;
    if (zcols > 0) {
        const int nv = zcols >> 2;
        for (int it = tid; it < 64 * nv; it += 256) {
            int r = it / nv, c = it % nv;
            *(float4*)&arow[(size_t)(m0 + r) * SEQ + zstart + c * 4] =
                make_float4(0.f, 0.f, 0.f, 0.f);
        }
    }
}

// ---------------------------------------------------------------------------
extern "C" void kernel_launch(void* const* d_in, const int* in_sizes, int n_in,
                              void* d_out, int out_size)
{
    const float* x  = (const float*)d_in[0];
    const float* Wq = (const float*)d_in[1];
    const float* bq = (const float*)d_in[2];
    const float* Wk = (const float*)d_in[3];
    const float* bk = (const float*)d_in[4];
    const float* Wv = (const float*)d_in[5];
    const float* bv = (const float*)d_in[6];
    const float* Wo = (const float*)d_in[7];
    const float* bo = (const float*)d_in[8];

    float* out = (float*)d_out;

    void *pq, *pk, *pv, *pctx, *pattn_scratch;
    cudaGetSymbolAddress(&pq, g_q);
    cudaGetSymbolAddress(&pk, g_k);
    cudaGetSymbolAddress(&pv, g_v);
    cudaGetSymbolAddress(&pctx, g_ctx);
    cudaGetSymbolAddress(&pattn_scratch, g_attn_scratch);

    float* attn = ((size_t)out_size >= OUT_ELEMS + ATTN_ELEMS)
                      ? out + OUT_ELEMS
                      : (float*)pattn_scratch;

    dim3 gProj(HID / 128, MROWS / 128);  // (8, 32)

    gemm128<<<gProj, 256>>>(x, Wq, bq, (float*)pq, MROWS, HID, HID);
    gemm128<<<gProj, 256>>>(x, Wk, bk, (float*)pk, MROWS, HID, HID);
    gemm128<<<gProj, 256>>>(x, Wv, bv, (float*)pv, MROWS, HID, HID);

    dim3 gAttn(SEQ / 64, BATCH * NH);  // (32, 32)
    attn_fused<<<gAttn, 256>>>((const float*)pq, (const float*)pk,
                               (const float*)pv, attn, (float*)pctx);

    gemm128<<<gProj, 256>>>((const float*)pctx, Wo, bo, out, MROWS, HID, HID);
}

// round 6
// speedup vs baseline: 1.6833x; 1.1133x over previous
#include <cuda_runtime.h>
#include <cuda_bf16.h>
#include <cstdint>
#include <math.h>

// Problem constants
#define BATCH 2
#define SEQ   2048
#define HID   1024
#define NH    16
#define HD    64
#define MROWS (BATCH * SEQ)   // 4096

static const size_t OUT_ELEMS  = (size_t)BATCH * SEQ * HID;              // 4,194,304
static const size_t ATTN_ELEMS = (size_t)BATCH * NH * SEQ * (size_t)SEQ; // 134,217,728

// Scratch (allocation-free: __device__ globals)
__device__ __align__(16) float g_q[MROWS * HID];
__device__ __align__(16) float g_k[MROWS * HID];
__device__ __align__(16) float g_v[MROWS * HID];
__device__ __align__(16) float g_ctx[MROWS * HID];
__device__ __align__(16) float g_attn_scratch[(size_t)BATCH * NH * SEQ * (size_t)SEQ];

// bf16 hi/lo split scratch
__device__ __align__(16) __nv_bfloat16 g_ah[MROWS * HID];   // activations hi
__device__ __align__(16) __nv_bfloat16 g_al[MROWS * HID];   // activations lo
__device__ __align__(16) __nv_bfloat16 g_wh[4 * HID * HID]; // weights hi (q,k,v,o)
__device__ __align__(16) __nv_bfloat16 g_wl[4 * HID * HID]; // weights lo

// ---------------------------------------------------------------------------
// PTX helpers (baseline sm_80+ features only — no tcgen05 on this toolchain)
// ---------------------------------------------------------------------------
typedef unsigned long long ull;

__device__ __forceinline__ ull dup2(float a) {
    ull r; asm("mov.b64 %0, {%1, %1};" : "=l"(r) : "f"(a)); return r;
}
__device__ __forceinline__ ull pk2(float x, float y) {
    ull r; asm("mov.b64 %0, {%1, %2};" : "=l"(r) : "f"(x), "f"(y)); return r;
}
__device__ __forceinline__ void ffma2(ull& d, ull a, ull b) {
    asm("fma.rn.f32x2 %0, %1, %2, %3;" : "=l"(d) : "l"(a), "l"(b), "l"(d));
}
__device__ __forceinline__ float2 unp2(ull v) {
    float2 f; asm("mov.b64 {%0, %1}, %2;" : "=f"(f.x), "=f"(f.y) : "l"(v)); return f;
}

__device__ __forceinline__ uint32_t smem_u32(const void* p) {
    uint32_t a;
    asm("{ .reg .u64 t; cvta.to.shared.u64 t, %1; cvt.u32.u64 %0, t; }" : "=r"(a) : "l"(p));
    return a;
}

#define CP_ASYNC16(dst, src) \
    asm volatile("cp.async.cg.shared.global [%0], [%1], 16;" :: "r"(dst), "l"(src) : "memory")
#define CP_COMMIT() asm volatile("cp.async.commit_group;" ::: "memory")
#define CP_WAIT(N)  asm volatile("cp.async.wait_group %0;" :: "n"(N) : "memory")

#define LDM4(r, a)                                                              \
    asm volatile("ldmatrix.sync.aligned.m8n8.x4.shared.b16 {%0,%1,%2,%3}, [%4];" \
                 : "=r"((r)[0]), "=r"((r)[1]), "=r"((r)[2]), "=r"((r)[3]) : "r"(a))

#define MMA16816(c, a, b)                                                       \
    asm volatile("mma.sync.aligned.m16n8k16.row.col.f32.bf16.bf16.f32 "         \
                 "{%0,%1,%2,%3}, {%4,%5,%6,%7}, {%8,%9}, {%0,%1,%2,%3};"        \
                 : "+f"((c)[0]), "+f"((c)[1]), "+f"((c)[2]), "+f"((c)[3])       \
                 : "r"((a)[0]), "r"((a)[1]), "r"((a)[2]), "r"((a)[3]),          \
                   "r"((b)[0]), "r"((b)[1]))

// ---------------------------------------------------------------------------
// fp32 -> bf16 hi/lo split
// ---------------------------------------------------------------------------
__global__ __launch_bounds__(256) void conv_split(
    const float* __restrict__ src, __nv_bfloat16* __restrict__ hi,
    __nv_bfloat16* __restrict__ lo, int n)
{
    int i = (blockIdx.x * 256 + threadIdx.x) * 4;
    if (i >= n) return;
    float4 v = *(const float4*)&src[i];
    __nv_bfloat16 h0 = __float2bfloat16(v.x), h1 = __float2bfloat16(v.y);
    __nv_bfloat16 h2 = __float2bfloat16(v.z), h3 = __float2bfloat16(v.w);
    __nv_bfloat16 l0 = __float2bfloat16(v.x - __bfloat162float(h0));
    __nv_bfloat16 l1 = __float2bfloat16(v.y - __bfloat162float(h1));
    __nv_bfloat16 l2 = __float2bfloat16(v.z - __bfloat162float(h2));
    __nv_bfloat16 l3 = __float2bfloat16(v.w - __bfloat162float(h3));
    *(__nv_bfloat162*)&hi[i]     = __nv_bfloat162(h0, h1);
    *(__nv_bfloat162*)&hi[i + 2] = __nv_bfloat162(h2, h3);
    *(__nv_bfloat162*)&lo[i]     = __nv_bfloat162(l0, l1);
    *(__nv_bfloat162*)&lo[i + 2] = __nv_bfloat162(l2, l3);
}

// ---------------------------------------------------------------------------
// Tensor-core (mma.sync bf16) 3-split GEMM:
//   C[M,N] = Ah@Bh^T + Ah@Bl^T + Al@Bh^T + bias
// BM=128, BN=128, BK=32. 256 threads = 8 warps, warp tile 64x32.
// cp.async double-buffered. Smem row stride 40 bf16 (80 B) -> conflict-free
// ldmatrix (80/4=20 banks/row; 8 rows hit distinct banks).
// ---------------------------------------------------------------------------
#define GM_STEPS (HID / 32)          // 32
#define GM_TPAD  80                  // bytes per smem row (40 bf16)
#define GM_TILE  (128 * GM_TPAD)     // 10240 B per operand tile
#define GM_BUF   (4 * GM_TILE)       // Ah,Al,Bh,Bl = 40960 B
#define GM_SMEM  (2 * GM_BUF)        // 81920 B

__global__ __launch_bounds__(256, 1) void gemm_mma(
    const __nv_bfloat16* __restrict__ Ah, const __nv_bfloat16* __restrict__ Al,
    const __nv_bfloat16* __restrict__ Bh, const __nv_bfloat16* __restrict__ Bl,
    const float* __restrict__ bias, float* __restrict__ C, int M, int N)
{
    extern __shared__ __align__(128) char sm[];
    const uint32_t smb = smem_u32(sm);
    const int tid = threadIdx.x;
    const int lane = tid & 31, w = tid >> 5;
    const int wr = w >> 2;   // 0..1  -> 64-row band
    const int wc = w & 3;    // 0..3  -> 32-col band
    const int m0 = blockIdx.y * 128, n0 = blockIdx.x * 128;
    const int K = HID;

    const __nv_bfloat16* gb[4] = {
        Ah + (size_t)m0 * K, Al + (size_t)m0 * K,
        Bh + (size_t)n0 * K, Bl + (size_t)n0 * K };

    // load one k-step (4 tiles of 128x32 bf16) into buffer b
    auto load_step = [&](int b, int k0) {
        uint32_t bufb = smb + b * GM_BUF;
        #pragma unroll
        for (int j = 0; j < 8; j++) {
            int i = tid + j * 256;              // 0..2047
            int t = i >> 9;                     // tile 0..3
            int r = (i >> 2) & 127;             // row
            int c = i & 3;                      // 16B chunk
            const __nv_bfloat16* src = gb[t] + (size_t)r * K + k0 + c * 8;
            uint32_t dst = bufb + t * GM_TILE + r * GM_TPAD + c * 16;
            CP_ASYNC16(dst, src);
        }
    };

    float acc[4][4][4];   // [mi][nt][reg]
    #pragma unroll
    for (int mi = 0; mi < 4; mi++)
        #pragma unroll
        for (int nt = 0; nt < 4; nt++)
            #pragma unroll
            for (int r = 0; r < 4; r++) acc[mi][nt][r] = 0.f;

    // per-lane ldmatrix source addresses (byte offsets within a tile)
    const uint32_t a_off = (uint32_t)(wr * 64 + (lane & 15)) * GM_TPAD + (lane >> 4) * 16;
    const int q = lane >> 3;   // B: 4 matrices per x4
    const uint32_t b_off = (uint32_t)(wc * 32 + (q >> 1) * 8 + (lane & 7)) * GM_TPAD
                         + (q & 1) * 16;

    load_step(0, 0);
    CP_COMMIT();

    for (int t = 0; t < GM_STEPS; t++) {
        if (t + 1 < GM_STEPS) {
            load_step((t + 1) & 1, (t + 1) * 32);
            CP_COMMIT();
            CP_WAIT(1);
        } else {
            CP_WAIT(0);
        }
        __syncthreads();

        const uint32_t bb = smb + (t & 1) * GM_BUF;
        #pragma unroll
        for (int kk = 0; kk < 2; kk++) {
            const uint32_t kb = kk * 32;   // 16 bf16 = 32 B
            uint32_t af[4][4], bh[4][2], bl[4][2];

            // B hi/lo fragments: 2 x4-ldmatrix each cover 2 n8-tiles
            #pragma unroll
            for (int p = 0; p < 2; p++) {
                uint32_t rb = bb + 2 * GM_TILE + b_off + p * 16 * GM_TPAD + kb;
                uint32_t tmp[4];
                LDM4(tmp, rb);
                bh[2 * p][0] = tmp[0]; bh[2 * p][1] = tmp[1];
                bh[2 * p + 1][0] = tmp[2]; bh[2 * p + 1][1] = tmp[3];
                LDM4(tmp, rb + GM_TILE);
                bl[2 * p][0] = tmp[0]; bl[2 * p][1] = tmp[1];
                bl[2 * p + 1][0] = tmp[2]; bl[2 * p + 1][1] = tmp[3];
            }

            // Ah fragments -> mma with Bh and Bl
            #pragma unroll
            for (int mi = 0; mi < 4; mi++) {
                LDM4(af[mi], bb + a_off + (uint32_t)mi * 16 * GM_TPAD + kb);
            }
            #pragma unroll
            for (int mi = 0; mi < 4; mi++)
                #pragma unroll
                for (int nt = 0; nt < 4; nt++) {
                    MMA16816(acc[mi][nt], af[mi], bh[nt]);
                    MMA16816(acc[mi][nt], af[mi], bl[nt]);
                }

            // Al fragments -> mma with Bh
            #pragma unroll
            for (int mi = 0; mi < 4; mi++) {
                LDM4(af[mi], bb + GM_TILE + a_off + (uint32_t)mi * 16 * GM_TPAD + kb);
            }
            #pragma unroll
            for (int mi = 0; mi < 4; mi++)
                #pragma unroll
                for (int nt = 0; nt < 4; nt++)
                    MMA16816(acc[mi][nt], af[mi], bh[nt]);
        }
        __syncthreads();
    }

    // epilogue
    const int rbase = m0 + wr * 64 + (lane >> 2);
    #pragma unroll
    for (int nt = 0; nt < 4; nt++) {
        const int col = n0 + wc * 32 + nt * 8 + (lane & 3) * 2;
        const float2 bv = *(const float2*)&bias[col];
        #pragma unroll
        for (int mi = 0; mi < 4; mi++) {
            int r0 = rbase + mi * 16;
            *(float2*)&C[(size_t)r0 * N + col] =
                make_float2(acc[mi][nt][0] + bv.x, acc[mi][nt][1] + bv.y);
            *(float2*)&C[(size_t)(r0 + 8) * N + col] =
                make_float2(acc[mi][nt][2] + bv.x, acc[mi][nt][3] + bv.y);
        }
    }
}

// ---------------------------------------------------------------------------
// Fused causal attention, recompute variant. Per (bh, 64-row tile):
//  phase 1: S = 8*QK^T per tile, online (m,l) stats only (no gmem writes)
//  phase 2: recompute S, write normalized probs once, accumulate ctx += P V
// ---------------------------------------------------------------------------
#define SD 68
#define ATTN_SMEM (3 * 64 * SD * 4)   // Qs, Ks, Vs = 52224 B

__global__ __launch_bounds__(256, 3) void attn_fused(
    const float* __restrict__ q, const float* __restrict__ k,
    const float* __restrict__ v, float* __restrict__ attn,
    float* __restrict__ ctx)
{
    extern __shared__ float smf[];
    float (*Qs)[SD] = (float(*)[SD])smf;             // [d][i] Q^T (persistent)
    float (*Ks)[SD] = (float(*)[SD])(smf + 64 * SD); // [d][j] K^T / later [j][i] P^T
    float (*Vs)[SD] = (float(*)[SD])(smf + 128 * SD);// [j][d] V

    const int tid = threadIdx.x;
    const int tx = tid & 15, ty = tid >> 4;
    const int mt = gridDim.x - 1 - blockIdx.x;  // heavy tiles first
    const int bh = blockIdx.y;
    const int b = bh >> 4, h = bh & 15;
    const int m0 = mt * 64;

    const float* Q  = q + (size_t)b * SEQ * HID + h * HD;
    const float* Kp = k + (size_t)b * SEQ * HID + h * HD;
    const float* Vp = v + (size_t)b * SEQ * HID + h * HD;
    float* arow = attn + (size_t)bh * SEQ * SEQ;

    // load Q tile transposed: Qs[d][i]
    for (int it = tid; it < 64 * 16; it += 256) {
        int r = it >> 4;
        int c = (it & 15) << 2;
        float4 vq = *(const float4*)&Q[(size_t)(m0 + r) * HID + c];
        Qs[c + 0][r] = vq.x; Qs[c + 1][r] = vq.y;
        Qs[c + 2][r] = vq.z; Qs[c + 3][r] = vq.w;
    }

    float m_[4] = {-INFINITY, -INFINITY, -INFINITY, -INFINITY};
    float l_[4] = {0.f, 0.f, 0.f, 0.f};

    // ---------------- phase 1: stats only ----------------
    for (int jt = 0; jt <= mt; jt++) {
        for (int it = tid; it < 64 * 16; it += 256) {
            int r = it >> 4;
            int c = (it & 15) << 2;
            float4 kv = *(const float4*)&Kp[(size_t)(jt * 64 + r) * HID + c];
            Ks[c + 0][r] = kv.x; Ks[c + 1][r] = kv.y;
            Ks[c + 2][r] = kv.z; Ks[c + 3][r] = kv.w;
        }
        __syncthreads();

        ull sacc[4][2];
        #pragma unroll
        for (int i = 0; i < 4; i++) { sacc[i][0] = 0ull; sacc[i][1] = 0ull; }

        #pragma unroll
        for (int d = 0; d < 64; d++) {
            float4 qa = *(float4*)&Qs[d][ty * 4];
            float4 kb = *(float4*)&Ks[d][tx * 4];
            ull b01 = pk2(kb.x, kb.y), b23 = pk2(kb.z, kb.w);
            float qv[4] = {qa.x, qa.y, qa.z, qa.w};
            #pragma unroll
            for (int i = 0; i < 4; i++) {
                ull ad = dup2(qv[i]);
                ffma2(sacc[i][0], ad, b01);
                ffma2(sacc[i][1], ad, b23);
            }
        }

        const int gj0 = jt * 64 + tx * 4;
        #pragma unroll
        for (int ii = 0; ii < 4; ii++) {
            float2 p0 = unp2(sacc[ii][0]);
            float2 p1 = unp2(sacc[ii][1]);
            const int gi = m0 + ty * 4 + ii;
            float t0 = (gj0 + 0 > gi) ? -INFINITY : p0.x * 8.0f;
            float t1 = (gj0 + 1 > gi) ? -INFINITY : p0.y * 8.0f;
            float t2 = (gj0 + 2 > gi) ? -INFINITY : p1.x * 8.0f;
            float t3 = (gj0 + 3 > gi) ? -INFINITY : p1.y * 8.0f;

            float tm = fmaxf(fmaxf(t0, t1), fmaxf(t2, t3));
            #pragma unroll
            for (int o = 1; o < 16; o <<= 1)
                tm = fmaxf(tm, __shfl_xor_sync(0xffffffffu, tm, o));
            float mnew = fmaxf(m_[ii], tm);

            float es = __expf(t0 - mnew) + __expf(t1 - mnew) +
                       __expf(t2 - mnew) + __expf(t3 - mnew);
            #pragma unroll
            for (int o = 1; o < 16; o <<= 1)
                es += __shfl_xor_sync(0xffffffffu, es, o);

            l_[ii] = l_[ii] * __expf(m_[ii] - mnew) + es;
            m_[ii] = mnew;
        }
        __syncthreads();
    }

    float invl[4];
    #pragma unroll
    for (int ii = 0; ii < 4; ii++) invl[ii] = 1.0f / l_[ii];

    // ---------------- phase 2: recompute, write P, accumulate ctx ----------
    ull cacc[4][2];
    #pragma unroll
    for (int i = 0; i < 4; i++) { cacc[i][0] = 0ull; cacc[i][1] = 0ull; }

    for (int jt = 0; jt <= mt; jt++) {
        for (int it = tid; it < 64 * 16; it += 256) {
            int r = it >> 4;
            int c = (it & 15) << 2;
            float4 kv = *(const float4*)&Kp[(size_t)(jt * 64 + r) * HID + c];
            Ks[c + 0][r] = kv.x; Ks[c + 1][r] = kv.y;
            Ks[c + 2][r] = kv.z; Ks[c + 3][r] = kv.w;
            *(float4*)&Vs[r][c] = *(const float4*)&Vp[(size_t)(jt * 64 + r) * HID + c];
        }
        __syncthreads();

        ull sacc[4][2];
        #pragma unroll
        for (int i = 0; i < 4; i++) { sacc[i][0] = 0ull; sacc[i][1] = 0ull; }
        #pragma unroll
        for (int d = 0; d < 64; d++) {
            float4 qa = *(float4*)&Qs[d][ty * 4];
            float4 kb = *(float4*)&Ks[d][tx * 4];
            ull b01 = pk2(kb.x, kb.y), b23 = pk2(kb.z, kb.w);
            float qv[4] = {qa.x, qa.y, qa.z, qa.w};
            #pragma unroll
            for (int i = 0; i < 4; i++) {
                ull ad = dup2(qv[i]);
                ffma2(sacc[i][0], ad, b01);
                ffma2(sacc[i][1], ad, b23);
            }
        }
        __syncthreads();   // everyone done reading Ks before P^T overwrite

        const int gj0 = jt * 64 + tx * 4;
        #pragma unroll
        for (int ii = 0; ii < 4; ii++) {
            const int gi = m0 + ty * 4 + ii;
            float2 p0 = unp2(sacc[ii][0]);
            float2 p1 = unp2(sacc[ii][1]);
            float q0 = (gj0 + 0 > gi) ? 0.f : __expf(p0.x * 8.0f - m_[ii]) * invl[ii];
            float q1 = (gj0 + 1 > gi) ? 0.f : __expf(p0.y * 8.0f - m_[ii]) * invl[ii];
            float q2 = (gj0 + 2 > gi) ? 0.f : __expf(p1.x * 8.0f - m_[ii]) * invl[ii];
            float q3 = (gj0 + 3 > gi) ? 0.f : __expf(p1.y * 8.0f - m_[ii]) * invl[ii];
            *(float4*)&arow[(size_t)gi * SEQ + gj0] = make_float4(q0, q1, q2, q3);
            // stage P^T into Ks
            Ks[tx * 4 + 0][ty * 4 + ii] = q0;
            Ks[tx * 4 + 1][ty * 4 + ii] = q1;
            Ks[tx * 4 + 2][ty * 4 + ii] = q2;
            Ks[tx * 4 + 3][ty * 4 + ii] = q3;
        }
        __syncthreads();

        #pragma unroll
        for (int j = 0; j < 64; j++) {
            float4 pv = *(float4*)&Ks[j][ty * 4];
            float4 vv = *(float4*)&Vs[j][tx * 4];
            ull v01 = pk2(vv.x, vv.y), v23 = pk2(vv.z, vv.w);
            float pvv[4] = {pv.x, pv.y, pv.z, pv.w};
            #pragma unroll
            for (int i = 0; i < 4; i++) {
                ull ad = dup2(pvv[i]);
                ffma2(cacc[i][0], ad, v01);
                ffma2(cacc[i][1], ad, v23);
            }
        }
        __syncthreads();
    }

    // write ctx
    #pragma unroll
    for (int ii = 0; ii < 4; ii++) {
        int gi = m0 + ty * 4 + ii;
        float2 c0 = unp2(cacc[ii][0]);
        float2 c1 = unp2(cacc[ii][1]);
        *(float4*)&ctx[((size_t)b * SEQ + gi) * HID + h * HD + tx * 4] =
            make_float4(c0.x, c0.y, c1.x, c1.y);
    }

    // zero-fill masked columns
    const int zstart = (mt + 1) * 64;
    const int zcols = SEQ - zstart;
    if (zcols > 0) {
        const int nv = zcols >> 2;
        for (int it = tid; it < 64 * nv; it += 256) {
            int r = it / nv, c = it % nv;
            *(float4*)&arow[(size_t)(m0 + r) * SEQ + zstart + c * 4] =
                make_float4(0.f, 0.f, 0.f, 0.f);
        }
    }
}

// ---------------------------------------------------------------------------
extern "C" void kernel_launch(void* const* d_in, const int* in_sizes, int n_in,
                              void* d_out, int out_size)
{
    const float* x  = (const float*)d_in[0];
    const float* Wq = (const float*)d_in[1];
    const float* bq = (const float*)d_in[2];
    const float* Wk = (const float*)d_in[3];
    const float* bk = (const float*)d_in[4];
    const float* Wv = (const float*)d_in[5];
    const float* bv = (const float*)d_in[6];
    const float* Wo = (const float*)d_in[7];
    const float* bo = (const float*)d_in[8];

    float* out = (float*)d_out;

    void *pq, *pk, *pv, *pctx, *pattn, *pah, *pal, *pwh, *pwl;
    cudaGetSymbolAddress(&pq, g_q);
    cudaGetSymbolAddress(&pk, g_k);
    cudaGetSymbolAddress(&pv, g_v);
    cudaGetSymbolAddress(&pctx, g_ctx);
    cudaGetSymbolAddress(&pattn, g_attn_scratch);
    cudaGetSymbolAddress(&pah, g_ah);
    cudaGetSymbolAddress(&pal, g_al);
    cudaGetSymbolAddress(&pwh, g_wh);
    cudaGetSymbolAddress(&pwl, g_wl);

    __nv_bfloat16* ah = (__nv_bfloat16*)pah;
    __nv_bfloat16* al = (__nv_bfloat16*)pal;
    __nv_bfloat16* wh = (__nv_bfloat16*)pwh;
    __nv_bfloat16* wl = (__nv_bfloat16*)pwl;

    float* attn = ((size_t)out_size >= OUT_ELEMS + ATTN_ELEMS)
                      ? out + OUT_ELEMS
                      : (float*)pattn;

    cudaFuncSetAttribute(gemm_mma, cudaFuncAttributeMaxDynamicSharedMemorySize, GM_SMEM);
    cudaFuncSetAttribute(attn_fused, cudaFuncAttributeMaxDynamicSharedMemorySize, ATTN_SMEM);

    const int NW = HID * HID;    // 1,048,576
    const int NX = MROWS * HID;  // 4,194,304

    // splits
    conv_split<<<NX / 1024, 256>>>(x, ah, al, NX);
    conv_split<<<NW / 1024, 256>>>(Wq, wh + 0 * (size_t)NW, wl + 0 * (size_t)NW, NW);
    conv_split<<<NW / 1024, 256>>>(Wk, wh + 1 * (size_t)NW, wl + 1 * (size_t)NW, NW);
    conv_split<<<NW / 1024, 256>>>(Wv, wh + 2 * (size_t)NW, wl + 2 * (size_t)NW, NW);
    conv_split<<<NW / 1024, 256>>>(Wo, wh + 3 * (size_t)NW, wl + 3 * (size_t)NW, NW);

    dim3 gG(HID / 128, MROWS / 128);  // (8, 32)
    gemm_mma<<<gG, 256, GM_SMEM>>>(ah, al, wh + 0 * (size_t)NW, wl + 0 * (size_t)NW,
                                   bq, (float*)pq, MROWS, HID);
    gemm_mma<<<gG, 256, GM_SMEM>>>(ah, al, wh + 1 * (size_t)NW, wl + 1 * (size_t)NW,
                                   bk, (float*)pk, MROWS, HID);
    gemm_mma<<<gG, 256, GM_SMEM>>>(ah, al, wh + 2 * (size_t)NW, wl + 2 * (size_t)NW,
                                   bv, (float*)pv, MROWS, HID);

    dim3 gAttn(SEQ / 64, BATCH * NH);  // (32, 32)
    attn_fused<<<gAttn, 256, ATTN_SMEM>>>((const float*)pq, (const float*)pk,
                                          (const float*)pv, attn, (float*)pctx);

    conv_split<<<NX / 1024, 256>>>((const float*)pctx, ah, al, NX);
    gemm_mma<<<gG, 256, GM_SMEM>>>(ah, al, wh + 3 * (size_t)NW, wl + 3 * (size_t)NW,
                                   bo, out, MROWS, HID);
}